// round 6
// baseline (speedup 1.0000x reference)
#include <cuda_runtime.h>
#include <cuda_fp16.h>
#include <cstdint>

#define BB    64
#define TT    512
#define DIN   512
#define DHID  1024
#define DOUT  512
#define NDAYS 24
#define EPS_  1e-5f

// Scratch (__device__ globals; no runtime allocation).
__device__ __half g_xh [(size_t)BB * TT * DIN];       // 32 MB x -> fp16
__device__ __half g_h  [(size_t)BB * TT * DHID];      // 64 MB hidden fp16
__device__ __half g_wt1[(size_t)NDAYS * DHID * DIN];  // 24 MB W1^T [d][n][k] fp16
__device__ __half g_wt2[(size_t)NDAYS * DOUT * DHID]; // 24 MB W2^T [d][n][k] fp16

// ---------------------------------------------------------------- helpers
__device__ __forceinline__ uint32_t smem_u32(const void* p) {
    uint32_t a;
    asm("{ .reg .u64 t; cvta.to.shared.u64 t, %1; cvt.u32.u64 %0, t; }"
        : "=r"(a) : "l"(p));
    return a;
}
__device__ __forceinline__ void cp16(uint32_t dst, const void* src) {
    asm volatile("cp.async.cg.shared.global [%0], [%1], 16;"
                 :: "r"(dst), "l"(src) : "memory");
}
__device__ __forceinline__ void ldm4(uint32_t& r0, uint32_t& r1,
                                     uint32_t& r2, uint32_t& r3, uint32_t a) {
    asm volatile("ldmatrix.sync.aligned.m8n8.x4.shared.b16 {%0,%1,%2,%3}, [%4];"
                 : "=r"(r0), "=r"(r1), "=r"(r2), "=r"(r3) : "r"(a));
}
__device__ __forceinline__ void mma16816(float* c, const uint32_t* a,
                                         uint32_t b0, uint32_t b1) {
    asm volatile(
        "mma.sync.aligned.m16n8k16.row.col.f32.f16.f16.f32 "
        "{%0,%1,%2,%3}, {%4,%5,%6,%7}, {%8,%9}, {%0,%1,%2,%3};"
        : "+f"(c[0]), "+f"(c[1]), "+f"(c[2]), "+f"(c[3])
        : "r"(a[0]), "r"(a[1]), "r"(a[2]), "r"(a[3]), "r"(b0), "r"(b1));
}

// ---------------------------------------------------------------- prep passes
__global__ __launch_bounds__(256) void cvt_x_kernel(const float4* __restrict__ in,
                                                    __half2* __restrict__ out, int n8) {
    int i = blockIdx.x * blockDim.x + threadIdx.x;
    if (i < n8) {
        float4 v0 = in[i * 2], v1 = in[i * 2 + 1];
        out[i * 4 + 0] = __floats2half2_rn(v0.x, v0.y);
        out[i * 4 + 1] = __floats2half2_rn(v0.z, v0.w);
        out[i * 4 + 2] = __floats2half2_rn(v1.x, v1.y);
        out[i * 4 + 3] = __floats2half2_rn(v1.z, v1.w);
    }
}

// W [NDAYS][K][N] fp32 -> Wt [NDAYS][N][K] fp16 (RNE).
template<int K, int N>
__global__ __launch_bounds__(256) void transpose_h_kernel(const float* __restrict__ W,
                                                          __half* __restrict__ Wt) {
    __shared__ float t[32][33];
    const int d  = blockIdx.z;
    const int n0 = blockIdx.x * 32;
    const int k0 = blockIdx.y * 32;
    const float* Wd  = W  + (size_t)d * K * N;
    __half*      Wtd = Wt + (size_t)d * N * K;
    const int tx = threadIdx.x, ty = threadIdx.y;  // 32 x 8
    #pragma unroll
    for (int r = 0; r < 32; r += 8)
        t[ty + r][tx] = Wd[(size_t)(k0 + ty + r) * N + n0 + tx];
    __syncthreads();
    #pragma unroll
    for (int r = 0; r < 32; r += 8)
        Wtd[(size_t)(n0 + ty + r) * K + k0 + tx] = __float2half_rn(t[tx][ty + r]);
}

// ---------------------------------------------------------------- FP16 GEMM
// C[b, m0:+128, n0:+128] = act( A[b] @ Wt[day[b]]^T + bias )
// 128 threads, 4 warps as 2(M) x 2(N); warp tile 64x64.
// K-chunk = 64 (4 x k16 steps), 3-stage cp.async pipeline.
#define STAGES 3
#define STAGE_BYTES 32768   // A 16KB + B 16KB  (128 rows x 128B each)
#define SMEM_DYN (STAGES * STAGE_BYTES)

template<int KDIM, int NTOT, bool RELU, typename CT>
__global__ __launch_bounds__(128, 2) void gemm_mma(
    const __half* __restrict__ A,
    const __half* __restrict__ Wt,
    const float*  __restrict__ bias,
    const int*    __restrict__ day,
    CT*           __restrict__ C)
{
    extern __shared__ char smem[];
    const uint32_t sbase = smem_u32(smem);

    const int tid  = threadIdx.x;
    const int lane = tid & 31;
    const int wid  = tid >> 5;
    const int wm   = wid & 1;    // 0..1  (M)  -> m offset wm*64
    const int wn   = wid >> 1;   // 0..1  (N)  -> n offset wn*64

    const int b  = blockIdx.x;
    const int m0 = blockIdx.y * 128;
    const int n0 = blockIdx.z * 128;
    const int d  = __ldg(day + b);

    const __half* Arow = A  + (size_t)(b * TT + m0) * KDIM;
    const __half* Brow = Wt + ((size_t)d * NTOT + n0) * KDIM;

    const int lrow = tid >> 3;   // 0..15
    const int lchk = tid & 7;    // 16B chunk within a 128B (64-half) row

    constexpr int KT = KDIM / 64;

    // ---- stage loader: A tile [128][64]h + B tile [128][64]h, xor-swizzled
    auto load_stage = [&](int s, int kt) {
        const uint32_t as = sbase + s * STAGE_BYTES;
        const uint32_t bs = as + 16384;
        const __half* ag = Arow + kt * 64 + lchk * 8;
        const __half* bg = Brow + kt * 64 + lchk * 8;
        #pragma unroll
        for (int p = 0; p < 8; p++) {
            const int row = p * 16 + lrow;
            const uint32_t soff = row * 128 + ((lchk ^ (row & 7)) << 4);
            cp16(as + soff, ag + (size_t)row * KDIM);
            cp16(bs + soff, bg + (size_t)row * KDIM);
        }
        asm volatile("cp.async.commit_group;" ::: "memory");
    };

    load_stage(0, 0);
    load_stage(1, 1);

    float acc[4][8][4] = {};

    // ldmatrix lane geometry: row = base + (lane & 15), k-octet = lane >> 4
    const int lrow16 = lane & 15;
    const int lhi    = lane >> 4;      // 0 or 1

    for (int i = 0; i < KT; i++) {
        if (i + 1 < KT) asm volatile("cp.async.wait_group 1;" ::: "memory");
        else            asm volatile("cp.async.wait_group 0;" ::: "memory");
        __syncthreads();
        if (i + 2 < KT) load_stage((i + 2) % STAGES, i + 2);

        const uint32_t as = sbase + (i % STAGES) * STAGE_BYTES;
        const uint32_t bs = as + 16384;

        #pragma unroll
        for (int ks = 0; ks < 4; ks++) {          // k16 step; chunks 2ks, 2ks+1
            const int chk = 2 * ks + lhi;
            uint32_t af[4][4];
            #pragma unroll
            for (int mt = 0; mt < 4; mt++) {
                const int row = wm * 64 + mt * 16 + lrow16;
                ldm4(af[mt][0], af[mt][1], af[mt][2], af[mt][3],
                     as + row * 128 + ((chk ^ (row & 7)) << 4));
            }
            uint32_t bf[4][4];
            #pragma unroll
            for (int ntp = 0; ntp < 4; ntp++) {
                const int row = wn * 64 + ntp * 16 + lrow16;
                ldm4(bf[ntp][0], bf[ntp][1], bf[ntp][2], bf[ntp][3],
                     bs + row * 128 + ((chk ^ (row & 7)) << 4));
            }
            // bf[p]: r0=(n0-7,k0-7) r1=(n8-15,k0-7) r2=(n0-7,k8-15) r3=(n8-15,k8-15)
            #pragma unroll
            for (int mt = 0; mt < 4; mt++)
                #pragma unroll
                for (int nt = 0; nt < 8; nt++)
                    mma16816(acc[mt][nt], af[mt],
                             bf[nt >> 1][nt & 1], bf[nt >> 1][2 + (nt & 1)]);
        }
    }

    // ---- epilogue: bias (+relu), fp16 or fp32 output
    const int g   = lane >> 2;
    const int tig = lane & 3;
    const float* biasd = bias + (size_t)d * NTOT + n0 + wn * 64;
    CT* Cb = C + (size_t)(b * TT + m0 + wm * 64) * NTOT + n0 + wn * 64;

    #pragma unroll
    for (int nt = 0; nt < 8; nt++) {
        const int coff = nt * 8 + tig * 2;
        const float2 bb = *(const float2*)(biasd + coff);
        #pragma unroll
        for (int mt = 0; mt < 4; mt++) {
            const int r0 = mt * 16 + g;
            float2 v0, v1;
            v0.x = acc[mt][nt][0] + bb.x;  v0.y = acc[mt][nt][1] + bb.y;
            v1.x = acc[mt][nt][2] + bb.x;  v1.y = acc[mt][nt][3] + bb.y;
            if (RELU) {
                v0.x = fmaxf(v0.x, 0.0f); v0.y = fmaxf(v0.y, 0.0f);
                v1.x = fmaxf(v1.x, 0.0f); v1.y = fmaxf(v1.y, 0.0f);
            }
            if constexpr (sizeof(CT) == 2) {
                *(__half2*)((__half*)Cb + (size_t)r0 * NTOT + coff) =
                    __floats2half2_rn(v0.x, v0.y);
                *(__half2*)((__half*)Cb + (size_t)(r0 + 8) * NTOT + coff) =
                    __floats2half2_rn(v1.x, v1.y);
            } else {
                *(float2*)((float*)Cb + (size_t)r0 * NTOT + coff)       = v0;
                *(float2*)((float*)Cb + (size_t)(r0 + 8) * NTOT + coff) = v1;
            }
        }
    }
}

// ---------------------------------------------------------------- LayerNorm
__global__ __launch_bounds__(256) void ln_kernel(
    float*       __restrict__ y,      // [B*T, D_OUT], in-place
    const float* __restrict__ gamma,
    const float* __restrict__ beta,
    const int*   __restrict__ day)
{
    const int row = blockIdx.x;
    const int b   = row / TT;
    const int d   = __ldg(day + b);
    float* yr = y + (size_t)row * DOUT;

    const int tid = threadIdx.x;
    const float2 v = *(const float2*)(yr + tid * 2);

    float s  = v.x + v.y;
    float sq = v.x * v.x + v.y * v.y;
    #pragma unroll
    for (int off = 16; off; off >>= 1) {
        s  += __shfl_xor_sync(0xffffffffu, s,  off);
        sq += __shfl_xor_sync(0xffffffffu, sq, off);
    }
    __shared__ float ss[8], sqs[8];
    const int w = tid >> 5, l = tid & 31;
    if (l == 0) { ss[w] = s; sqs[w] = sq; }
    __syncthreads();
    if (w == 0) {
        s  = (l < 8) ? ss[l]  : 0.0f;
        sq = (l < 8) ? sqs[l] : 0.0f;
        #pragma unroll
        for (int off = 16; off; off >>= 1) {
            s  += __shfl_xor_sync(0xffffffffu, s,  off);
            sq += __shfl_xor_sync(0xffffffffu, sq, off);
        }
        if (l == 0) { ss[0] = s; sqs[0] = sq; }
    }
    __syncthreads();
    s = ss[0]; sq = sqs[0];

    const float mean = s * (1.0f / DOUT);
    const float var  = sq * (1.0f / DOUT) - mean * mean;
    const float inv  = rsqrtf(var + EPS_);

    const float2 g2 = *(const float2*)(gamma + (size_t)d * DOUT + tid * 2);
    const float2 b2 = *(const float2*)(beta  + (size_t)d * DOUT + tid * 2);
    float2 o;
    o.x = (v.x - mean) * inv * g2.x + b2.x;
    o.y = (v.y - mean) * inv * g2.y + b2.y;
    *(float2*)(yr + tid * 2) = o;
}

// ---------------------------------------------------------------- launch
extern "C" void kernel_launch(void* const* d_in, const int* in_sizes, int n_in,
                              void* d_out, int out_size)
{
    const float* x     = (const float*)d_in[0];
    const int*   day   = (const int*)  d_in[1];
    const float* W1    = (const float*)d_in[2];
    const float* b1    = (const float*)d_in[3];
    const float* W2    = (const float*)d_in[4];
    const float* b2    = (const float*)d_in[5];
    const float* gamma = (const float*)d_in[6];
    const float* beta  = (const float*)d_in[7];
    float* out = (float*)d_out;

    __half *xh, *h, *wt1, *wt2;
    cudaGetSymbolAddress((void**)&xh,  g_xh);
    cudaGetSymbolAddress((void**)&h,   g_h);
    cudaGetSymbolAddress((void**)&wt1, g_wt1);
    cudaGetSymbolAddress((void**)&wt2, g_wt2);

    // prep: convert x to fp16; transpose+convert W1, W2
    const int n8 = BB * TT * DIN / 8;
    cvt_x_kernel<<<(n8 + 255) / 256, 256>>>((const float4*)x, (__half2*)xh, n8);
    transpose_h_kernel<DIN,  DHID><<<dim3(DHID / 32, DIN  / 32, NDAYS), dim3(32, 8)>>>(W1, wt1);
    transpose_h_kernel<DHID, DOUT><<<dim3(DOUT / 32, DHID / 32, NDAYS), dim3(32, 8)>>>(W2, wt2);

    cudaFuncSetAttribute(gemm_mma<DIN,  DHID, true,  __half>,
                         cudaFuncAttributeMaxDynamicSharedMemorySize, SMEM_DYN);
    cudaFuncSetAttribute(gemm_mma<DHID, DOUT, false, float>,
                         cudaFuncAttributeMaxDynamicSharedMemorySize, SMEM_DYN);

    // GEMM1: xh @ W1^T -> h (fp16, bias+relu fused)
    gemm_mma<DIN,  DHID, true,  __half><<<dim3(BB, TT / 128, DHID / 128), 128, SMEM_DYN>>>(
        xh, wt1, b1, day, h);
    // GEMM2: h @ W2^T -> out (fp32, bias fused)
    gemm_mma<DHID, DOUT, false, float><<<dim3(BB, TT / 128, DOUT / 128), 128, SMEM_DYN>>>(
        h, wt2, b2, day, out);
    // LayerNorm in-place
    ln_kernel<<<BB * TT, 256>>>(out, gamma, beta, day);
}

// round 7
// speedup vs baseline: 1.0972x; 1.0972x over previous
#include <cuda_runtime.h>
#include <cuda_fp16.h>
#include <cstdint>

#define BB    64
#define TT    512
#define DIN   512
#define DHID  1024
#define DOUT  512
#define NDAYS 24
#define EPS_  1e-5f

// Scratch (__device__ globals; no runtime allocation).
__device__ __half g_xh [(size_t)BB * TT * DIN];       // 32 MB x -> fp16
__device__ __half g_h  [(size_t)BB * TT * DHID];      // 64 MB hidden fp16
__device__ __half g_wt1[(size_t)NDAYS * DHID * DIN];  // 24 MB W1^T [d][n][k] fp16
__device__ __half g_wt2[(size_t)NDAYS * DOUT * DHID]; // 24 MB W2^T [d][n][k] fp16

// ---------------------------------------------------------------- helpers
__device__ __forceinline__ uint32_t smem_u32(const void* p) {
    uint32_t a;
    asm("{ .reg .u64 t; cvta.to.shared.u64 t, %1; cvt.u32.u64 %0, t; }"
        : "=r"(a) : "l"(p));
    return a;
}
__device__ __forceinline__ void cp16(uint32_t dst, const void* src) {
    asm volatile("cp.async.cg.shared.global [%0], [%1], 16;"
                 :: "r"(dst), "l"(src) : "memory");
}
__device__ __forceinline__ void ldm4(uint32_t& r0, uint32_t& r1,
                                     uint32_t& r2, uint32_t& r3, uint32_t a) {
    asm volatile("ldmatrix.sync.aligned.m8n8.x4.shared.b16 {%0,%1,%2,%3}, [%4];"
                 : "=r"(r0), "=r"(r1), "=r"(r2), "=r"(r3) : "r"(a));
}
__device__ __forceinline__ void mma16816(float* c, const uint32_t* a,
                                         uint32_t b0, uint32_t b1) {
    asm volatile(
        "mma.sync.aligned.m16n8k16.row.col.f32.f16.f16.f32 "
        "{%0,%1,%2,%3}, {%4,%5,%6,%7}, {%8,%9}, {%0,%1,%2,%3};"
        : "+f"(c[0]), "+f"(c[1]), "+f"(c[2]), "+f"(c[3])
        : "r"(a[0]), "r"(a[1]), "r"(a[2]), "r"(a[3]), "r"(b0), "r"(b1));
}

// ---------------------------------------------------------------- fused prep
// W [NDAYS][K][N] fp32 -> Wt [NDAYS][N][K] fp16 (RNE), 32x32 tile.
template<int K, int N>
__device__ __forceinline__ void transpose_tile(const float* __restrict__ W,
                                               __half* __restrict__ Wt,
                                               int d, int n0, int k0,
                                               float (*t)[33], int tx, int ty) {
    const float* Wd  = W  + (size_t)d * K * N;
    __half*      Wtd = Wt + (size_t)d * N * K;
    #pragma unroll
    for (int r = 0; r < 32; r += 8)
        t[ty + r][tx] = Wd[(size_t)(k0 + ty + r) * N + n0 + tx];
    __syncthreads();
    #pragma unroll
    for (int r = 0; r < 32; r += 8)
        Wtd[(size_t)(n0 + ty + r) * K + k0 + tx] = __float2half_rn(t[tx][ty + r]);
}

#define NBLK_X  8192                  // (BB*TT*DIN/8)/256
#define NBLK_W1 (32 * 16 * NDAYS)     // (DHID/32)*(DIN/32)*NDAYS  = 12288
#define NBLK_W2 (16 * 32 * NDAYS)     // (DOUT/32)*(DHID/32)*NDAYS = 12288

__global__ __launch_bounds__(256) void prep_kernel(
    const float4* __restrict__ x, __half2* __restrict__ xh,
    const float* __restrict__ W1, __half* __restrict__ wt1,
    const float* __restrict__ W2, __half* __restrict__ wt2)
{
    __shared__ float t[32][33];
    const int blk = blockIdx.x;
    const int tid = threadIdx.x;
    if (blk < NBLK_X) {
        const int i = blk * 256 + tid;
        float4 v0 = x[i * 2], v1 = x[i * 2 + 1];
        xh[i * 4 + 0] = __floats2half2_rn(v0.x, v0.y);
        xh[i * 4 + 1] = __floats2half2_rn(v0.z, v0.w);
        xh[i * 4 + 2] = __floats2half2_rn(v1.x, v1.y);
        xh[i * 4 + 3] = __floats2half2_rn(v1.z, v1.w);
    } else if (blk < NBLK_X + NBLK_W1) {
        int r = blk - NBLK_X;
        const int d = r / (32 * 16); r %= 32 * 16;
        const int n0 = (r % 32) * 32;
        const int k0 = (r / 32) * 32;
        transpose_tile<DIN, DHID>(W1, wt1, d, n0, k0, t, tid & 31, tid >> 5);
    } else {
        int r = blk - NBLK_X - NBLK_W1;
        const int d = r / (16 * 32); r %= 16 * 32;
        const int n0 = (r % 16) * 32;
        const int k0 = (r / 16) * 32;
        transpose_tile<DHID, DOUT>(W2, wt2, d, n0, k0, t, tid & 31, tid >> 5);
    }
}

// ---------------------------------------------------------------- FP16 GEMM
// C[b, m0:+128, n0:+128] = act( A[b] @ Wt[day[b]]^T + bias )
// 256 threads, 8 warps 2(M) x 4(N); warp tile 64x32; K-chunk 64; 3 stages.
// Software-pipelined: frag double-buffer, mid-chunk wait+sync, spread cp.async.
#define STAGES 3
#define STAGE_BYTES 32768   // A 16KB + B 16KB  (128 rows x 128B each)
#define SMEM_DYN (STAGES * STAGE_BYTES)

template<int KDIM, int NTOT, bool RELU, typename CT>
__global__ __launch_bounds__(256, 2) void gemm_mma(
    const __half* __restrict__ A,
    const __half* __restrict__ Wt,
    const float*  __restrict__ bias,
    const int*    __restrict__ day,
    CT*           __restrict__ C)
{
    extern __shared__ char smem[];
    const uint32_t sbase = smem_u32(smem);

    const int tid  = threadIdx.x;
    const int lane = tid & 31;
    const int wid  = tid >> 5;
    const int wm   = wid & 1;    // M warp  -> m offset wm*64
    const int wn   = wid >> 1;   // N warp  -> n offset wn*32

    const int b  = blockIdx.x;
    const int m0 = blockIdx.y * 128;
    const int n0 = blockIdx.z * 128;
    const int d  = __ldg(day + b);

    const __half* Arow = A  + (size_t)(b * TT + m0) * KDIM;
    const __half* Brow = Wt + ((size_t)d * NTOT + n0) * KDIM;

    const int lrow = tid >> 3;   // 0..31
    const int lchk = tid & 7;    // 16B chunk within a 128B (64-half) row

    constexpr int KT = KDIM / 64;

    // one cp part = 1 A row + 1 B row (of this thread's 4 each)
    auto cp_part = [&](int s, int kt, int p) {
        const uint32_t as_ = sbase + s * STAGE_BYTES;
        const int row = p * 32 + lrow;
        const uint32_t soff = row * 128 + ((lchk ^ (row & 7)) << 4);
        const size_t goff = (size_t)kt * 64 + (size_t)row * KDIM + lchk * 8;
        cp16(as_ + soff,         Arow + goff);
        cp16(as_ + 16384 + soff, Brow + goff);
    };
    auto cp_stage = [&](int s, int kt) {
        #pragma unroll
        for (int p = 0; p < 4; p++) cp_part(s, kt, p);
        asm volatile("cp.async.commit_group;" ::: "memory");
    };

    // fragment loaders (ks = k16 step 0..3 within the 64-wide stage)
    const int lrow16 = lane & 15;
    const int lhi    = lane >> 4;
    auto load_afr = [&](uint32_t as_, int ks, uint32_t (*f)[4]) {
        const int chk = 2 * ks + lhi;
        #pragma unroll
        for (int mt = 0; mt < 4; mt++) {
            const int row = wm * 64 + mt * 16 + lrow16;
            ldm4(f[mt][0], f[mt][1], f[mt][2], f[mt][3],
                 as_ + row * 128 + (((row & 7) ^ chk) << 4));
        }
    };
    auto load_bfr = [&](uint32_t bs_, int ks, uint32_t (*f)[4]) {
        const int chk = 2 * ks + lhi;
        #pragma unroll
        for (int p = 0; p < 2; p++) {
            const int row = wn * 32 + p * 16 + lrow16;
            ldm4(f[p][0], f[p][1], f[p][2], f[p][3],
                 bs_ + row * 128 + (((row & 7) ^ chk) << 4));
        }
    };

    // prologue
    cp_stage(0, 0);
    cp_stage(1, 1);
    asm volatile("cp.async.wait_group 1;" ::: "memory");
    __syncthreads();

    float acc[4][4][4] = {};
    uint32_t af[2][4][4], bf[2][2][4];
    load_afr(sbase, 0, af[0]);
    load_bfr(sbase + 16384, 0, bf[0]);

    for (int i = 0; i < KT; i++) {
        const uint32_t as = sbase + (i % STAGES) * STAGE_BYTES;
        const uint32_t bs = as + 16384;
        const int inext = i + 2;
        const int snext = inext % STAGES;

        #pragma unroll
        for (int ks = 0; ks < 4; ks++) {
            const int cur = ks & 1, nxt = cur ^ 1;

            // prefetch fragments for the next k-step (or next chunk's ks=0)
            if (ks < 3) {
                load_afr(as, ks + 1, af[nxt]);
                load_bfr(bs, ks + 1, bf[nxt]);
            }
            // spread next-stage cp.async: one part per k-step
            if (inext < KT) cp_part(snext, inext, ks);

            if (ks == 2 && i + 1 < KT) {
                // stage i+1's group committed a chunk ago -> near-free wait.
                // Uncommitted (stage i+2) copies keep flying.
                asm volatile("cp.async.wait_group 0;" ::: "memory");
                __syncthreads();
                // post-barrier: MMAs below run on already-loaded frags
            }
            if (ks == 3) {
                if (inext < KT)
                    asm volatile("cp.async.commit_group;" ::: "memory");
                if (i + 1 < KT) {
                    const uint32_t as2 = sbase + ((i + 1) % STAGES) * STAGE_BYTES;
                    load_afr(as2, 0, af[nxt]);
                    load_bfr(as2 + 16384, 0, bf[nxt]);
                }
            }

            #pragma unroll
            for (int mt = 0; mt < 4; mt++)
                #pragma unroll
                for (int nt = 0; nt < 4; nt++)
                    mma16816(acc[mt][nt], af[cur][mt],
                             bf[cur][nt >> 1][nt & 1], bf[cur][nt >> 1][2 + (nt & 1)]);
        }
    }

    // ---- epilogue: bias (+relu), fp16 or fp32 output
    const int g   = lane >> 2;
    const int tig = lane & 3;
    const float* biasd = bias + (size_t)d * NTOT + n0 + wn * 32;
    CT* Cb = C + (size_t)(b * TT + m0 + wm * 64) * NTOT + n0 + wn * 32;

    #pragma unroll
    for (int nt = 0; nt < 4; nt++) {
        const int coff = nt * 8 + tig * 2;
        const float2 bb = *(const float2*)(biasd + coff);
        #pragma unroll
        for (int mt = 0; mt < 4; mt++) {
            const int r0 = mt * 16 + g;
            float2 v0, v1;
            v0.x = acc[mt][nt][0] + bb.x;  v0.y = acc[mt][nt][1] + bb.y;
            v1.x = acc[mt][nt][2] + bb.x;  v1.y = acc[mt][nt][3] + bb.y;
            if (RELU) {
                v0.x = fmaxf(v0.x, 0.0f); v0.y = fmaxf(v0.y, 0.0f);
                v1.x = fmaxf(v1.x, 0.0f); v1.y = fmaxf(v1.y, 0.0f);
            }
            if constexpr (sizeof(CT) == 2) {
                *(__half2*)((__half*)Cb + (size_t)r0 * NTOT + coff) =
                    __floats2half2_rn(v0.x, v0.y);
                *(__half2*)((__half*)Cb + (size_t)(r0 + 8) * NTOT + coff) =
                    __floats2half2_rn(v1.x, v1.y);
            } else {
                *(float2*)((float*)Cb + (size_t)r0 * NTOT + coff)       = v0;
                *(float2*)((float*)Cb + (size_t)(r0 + 8) * NTOT + coff) = v1;
            }
        }
    }
}

// ---------------------------------------------------------------- LayerNorm
__global__ __launch_bounds__(256) void ln_kernel(
    float*       __restrict__ y,      // [B*T, D_OUT], in-place
    const float* __restrict__ gamma,
    const float* __restrict__ beta,
    const int*   __restrict__ day)
{
    const int row = blockIdx.x;
    const int b   = row / TT;
    const int d   = __ldg(day + b);
    float* yr = y + (size_t)row * DOUT;

    const int tid = threadIdx.x;
    const float2 v = *(const float2*)(yr + tid * 2);

    float s  = v.x + v.y;
    float sq = v.x * v.x + v.y * v.y;
    #pragma unroll
    for (int off = 16; off; off >>= 1) {
        s  += __shfl_xor_sync(0xffffffffu, s,  off);
        sq += __shfl_xor_sync(0xffffffffu, sq, off);
    }
    __shared__ float ss[8], sqs[8];
    const int w = tid >> 5, l = tid & 31;
    if (l == 0) { ss[w] = s; sqs[w] = sq; }
    __syncthreads();
    if (w == 0) {
        s  = (l < 8) ? ss[l]  : 0.0f;
        sq = (l < 8) ? sqs[l] : 0.0f;
        #pragma unroll
        for (int off = 16; off; off >>= 1) {
            s  += __shfl_xor_sync(0xffffffffu, s,  off);
            sq += __shfl_xor_sync(0xffffffffu, sq, off);
        }
        if (l == 0) { ss[0] = s; sqs[0] = sq; }
    }
    __syncthreads();
    s = ss[0]; sq = sqs[0];

    const float mean = s * (1.0f / DOUT);
    const float var  = sq * (1.0f / DOUT) - mean * mean;
    const float inv  = rsqrtf(var + EPS_);

    const float2 g2 = *(const float2*)(gamma + (size_t)d * DOUT + tid * 2);
    const float2 b2 = *(const float2*)(beta  + (size_t)d * DOUT + tid * 2);
    float2 o;
    o.x = (v.x - mean) * inv * g2.x + b2.x;
    o.y = (v.y - mean) * inv * g2.y + b2.y;
    *(float2*)(yr + tid * 2) = o;
}

// ---------------------------------------------------------------- launch
extern "C" void kernel_launch(void* const* d_in, const int* in_sizes, int n_in,
                              void* d_out, int out_size)
{
    const float* x     = (const float*)d_in[0];
    const int*   day   = (const int*)  d_in[1];
    const float* W1    = (const float*)d_in[2];
    const float* b1    = (const float*)d_in[3];
    const float* W2    = (const float*)d_in[4];
    const float* b2    = (const float*)d_in[5];
    const float* gamma = (const float*)d_in[6];
    const float* beta  = (const float*)d_in[7];
    float* out = (float*)d_out;

    __half *xh, *h, *wt1, *wt2;
    cudaGetSymbolAddress((void**)&xh,  g_xh);
    cudaGetSymbolAddress((void**)&h,   g_h);
    cudaGetSymbolAddress((void**)&wt1, g_wt1);
    cudaGetSymbolAddress((void**)&wt2, g_wt2);

    // fused prep: convert x + transpose/convert W1, W2 in one launch
    prep_kernel<<<NBLK_X + NBLK_W1 + NBLK_W2, 256>>>(
        (const float4*)x, (__half2*)xh, W1, wt1, W2, wt2);

    cudaFuncSetAttribute(gemm_mma<DIN,  DHID, true,  __half>,
                         cudaFuncAttributeMaxDynamicSharedMemorySize, SMEM_DYN);
    cudaFuncSetAttribute(gemm_mma<DHID, DOUT, false, float>,
                         cudaFuncAttributeMaxDynamicSharedMemorySize, SMEM_DYN);

    // GEMM1: xh @ W1^T -> h (fp16, bias+relu fused)
    gemm_mma<DIN,  DHID, true,  __half><<<dim3(BB, TT / 128, DHID / 128), 256, SMEM_DYN>>>(
        xh, wt1, b1, day, h);
    // GEMM2: h @ W2^T -> out (fp32, bias fused)
    gemm_mma<DHID, DOUT, false, float><<<dim3(BB, TT / 128, DOUT / 128), 256, SMEM_DYN>>>(
        h, wt2, b2, day, out);
    // LayerNorm in-place
    ln_kernel<<<BB * TT, 256>>>(out, gamma, beta, day);
}

// round 8
// speedup vs baseline: 1.1963x; 1.0904x over previous
#include <cuda_runtime.h>
#include <cuda_fp16.h>
#include <cstdint>

#define BB    64
#define TT    512
#define DIN   512
#define DHID  1024
#define DOUT  512
#define NDAYS 24
#define EPS_  1e-5f

// Scratch (__device__ globals; no runtime allocation).
__device__ __half g_xh [(size_t)BB * TT * DIN];       // 32 MB x -> fp16
__device__ __half g_h  [(size_t)BB * TT * DHID];      // 64 MB hidden fp16
__device__ __half g_wt1[(size_t)NDAYS * DHID * DIN];  // 24 MB W1^T [d][n][k] fp16
__device__ __half g_wt2[(size_t)NDAYS * DOUT * DHID]; // 24 MB W2^T [d][n][k] fp16

// ---------------------------------------------------------------- helpers
__device__ __forceinline__ uint32_t smem_u32(const void* p) {
    uint32_t a;
    asm("{ .reg .u64 t; cvta.to.shared.u64 t, %1; cvt.u32.u64 %0, t; }"
        : "=r"(a) : "l"(p));
    return a;
}
__device__ __forceinline__ void cp16(uint32_t dst, const void* src) {
    asm volatile("cp.async.cg.shared.global [%0], [%1], 16;"
                 :: "r"(dst), "l"(src) : "memory");
}
__device__ __forceinline__ void ldm4(uint32_t& r0, uint32_t& r1,
                                     uint32_t& r2, uint32_t& r3, uint32_t a) {
    asm volatile("ldmatrix.sync.aligned.m8n8.x4.shared.b16 {%0,%1,%2,%3}, [%4];"
                 : "=r"(r0), "=r"(r1), "=r"(r2), "=r"(r3) : "r"(a));
}
__device__ __forceinline__ void mma16816(float* c, const uint32_t* a,
                                         uint32_t b0, uint32_t b1) {
    asm volatile(
        "mma.sync.aligned.m16n8k16.row.col.f32.f16.f16.f32 "
        "{%0,%1,%2,%3}, {%4,%5,%6,%7}, {%8,%9}, {%0,%1,%2,%3};"
        : "+f"(c[0]), "+f"(c[1]), "+f"(c[2]), "+f"(c[3])
        : "r"(a[0]), "r"(a[1]), "r"(a[2]), "r"(a[3]), "r"(b0), "r"(b1));
}

// ---------------------------------------------------------------- fused prep
template<int K, int N>
__device__ __forceinline__ void transpose_tile(const float* __restrict__ W,
                                               __half* __restrict__ Wt,
                                               int d, int n0, int k0,
                                               float (*t)[33], int tx, int ty) {
    const float* Wd  = W  + (size_t)d * K * N;
    __half*      Wtd = Wt + (size_t)d * N * K;
    #pragma unroll
    for (int r = 0; r < 32; r += 8)
        t[ty + r][tx] = Wd[(size_t)(k0 + ty + r) * N + n0 + tx];
    __syncthreads();
    #pragma unroll
    for (int r = 0; r < 32; r += 8)
        Wtd[(size_t)(n0 + ty + r) * K + k0 + tx] = __float2half_rn(t[tx][ty + r]);
}

#define NBLK_X  8192                  // (BB*TT*DIN/8)/256
#define NBLK_W1 (32 * 16 * NDAYS)     // 12288
#define NBLK_W2 (16 * 32 * NDAYS)     // 12288

__global__ __launch_bounds__(256) void prep_kernel(
    const float4* __restrict__ x, __half2* __restrict__ xh,
    const float* __restrict__ W1, __half* __restrict__ wt1,
    const float* __restrict__ W2, __half* __restrict__ wt2)
{
    __shared__ float t[32][33];
    const int blk = blockIdx.x;
    const int tid = threadIdx.x;
    if (blk < NBLK_X) {
        const int i = blk * 256 + tid;
        float4 v0 = x[i * 2], v1 = x[i * 2 + 1];
        xh[i * 4 + 0] = __floats2half2_rn(v0.x, v0.y);
        xh[i * 4 + 1] = __floats2half2_rn(v0.z, v0.w);
        xh[i * 4 + 2] = __floats2half2_rn(v1.x, v1.y);
        xh[i * 4 + 3] = __floats2half2_rn(v1.z, v1.w);
    } else if (blk < NBLK_X + NBLK_W1) {
        int r = blk - NBLK_X;
        const int d = r / (32 * 16); r %= 32 * 16;
        const int n0 = (r % 32) * 32;
        const int k0 = (r / 32) * 32;
        transpose_tile<DIN, DHID>(W1, wt1, d, n0, k0, t, tid & 31, tid >> 5);
    } else {
        int r = blk - NBLK_X - NBLK_W1;
        const int d = r / (16 * 32); r %= 16 * 32;
        const int n0 = (r % 16) * 32;
        const int k0 = (r / 16) * 32;
        transpose_tile<DHID, DOUT>(W2, wt2, d, n0, k0, t, tid & 31, tid >> 5);
    }
}

// ---------------------------------------------------------------- FP16 GEMM
// (unchanged from R7: 256 thr, 2Mx4N warps of 64x32, K-chunk 64, 3 stages,
//  software-pipelined frags + spread cp.async)
#define STAGES 3
#define STAGE_BYTES 32768
#define SMEM_DYN (STAGES * STAGE_BYTES)

template<int KDIM, int NTOT, bool RELU, typename CT>
__global__ __launch_bounds__(256, 2) void gemm_mma(
    const __half* __restrict__ A,
    const __half* __restrict__ Wt,
    const float*  __restrict__ bias,
    const int*    __restrict__ day,
    CT*           __restrict__ C)
{
    extern __shared__ char smem[];
    const uint32_t sbase = smem_u32(smem);

    const int tid  = threadIdx.x;
    const int lane = tid & 31;
    const int wid  = tid >> 5;
    const int wm   = wid & 1;
    const int wn   = wid >> 1;

    const int b  = blockIdx.x;
    const int m0 = blockIdx.y * 128;
    const int n0 = blockIdx.z * 128;
    const int d  = __ldg(day + b);

    const __half* Arow = A  + (size_t)(b * TT + m0) * KDIM;
    const __half* Brow = Wt + ((size_t)d * NTOT + n0) * KDIM;

    const int lrow = tid >> 3;
    const int lchk = tid & 7;

    constexpr int KT = KDIM / 64;

    auto cp_part = [&](int s, int kt, int p) {
        const uint32_t as_ = sbase + s * STAGE_BYTES;
        const int row = p * 32 + lrow;
        const uint32_t soff = row * 128 + ((lchk ^ (row & 7)) << 4);
        const size_t goff = (size_t)kt * 64 + (size_t)row * KDIM + lchk * 8;
        cp16(as_ + soff,         Arow + goff);
        cp16(as_ + 16384 + soff, Brow + goff);
    };
    auto cp_stage = [&](int s, int kt) {
        #pragma unroll
        for (int p = 0; p < 4; p++) cp_part(s, kt, p);
        asm volatile("cp.async.commit_group;" ::: "memory");
    };

    const int lrow16 = lane & 15;
    const int lhi    = lane >> 4;
    auto load_afr = [&](uint32_t as_, int ks, uint32_t (*f)[4]) {
        const int chk = 2 * ks + lhi;
        #pragma unroll
        for (int mt = 0; mt < 4; mt++) {
            const int row = wm * 64 + mt * 16 + lrow16;
            ldm4(f[mt][0], f[mt][1], f[mt][2], f[mt][3],
                 as_ + row * 128 + (((row & 7) ^ chk) << 4));
        }
    };
    auto load_bfr = [&](uint32_t bs_, int ks, uint32_t (*f)[4]) {
        const int chk = 2 * ks + lhi;
        #pragma unroll
        for (int p = 0; p < 2; p++) {
            const int row = wn * 32 + p * 16 + lrow16;
            ldm4(f[p][0], f[p][1], f[p][2], f[p][3],
                 bs_ + row * 128 + (((row & 7) ^ chk) << 4));
        }
    };

    cp_stage(0, 0);
    cp_stage(1, 1);
    asm volatile("cp.async.wait_group 1;" ::: "memory");
    __syncthreads();

    float acc[4][4][4] = {};
    uint32_t af[2][4][4], bf[2][2][4];
    load_afr(sbase, 0, af[0]);
    load_bfr(sbase + 16384, 0, bf[0]);

    for (int i = 0; i < KT; i++) {
        const uint32_t as = sbase + (i % STAGES) * STAGE_BYTES;
        const uint32_t bs = as + 16384;
        const int inext = i + 2;
        const int snext = inext % STAGES;

        #pragma unroll
        for (int ks = 0; ks < 4; ks++) {
            const int cur = ks & 1, nxt = cur ^ 1;

            if (ks < 3) {
                load_afr(as, ks + 1, af[nxt]);
                load_bfr(bs, ks + 1, bf[nxt]);
            }
            if (inext < KT) cp_part(snext, inext, ks);

            if (ks == 2 && i + 1 < KT) {
                asm volatile("cp.async.wait_group 0;" ::: "memory");
                __syncthreads();
            }
            if (ks == 3) {
                if (inext < KT)
                    asm volatile("cp.async.commit_group;" ::: "memory");
                if (i + 1 < KT) {
                    const uint32_t as2 = sbase + ((i + 1) % STAGES) * STAGE_BYTES;
                    load_afr(as2, 0, af[nxt]);
                    load_bfr(as2 + 16384, 0, bf[nxt]);
                }
            }

            #pragma unroll
            for (int mt = 0; mt < 4; mt++)
                #pragma unroll
                for (int nt = 0; nt < 4; nt++)
                    mma16816(acc[mt][nt], af[cur][mt],
                             bf[cur][nt >> 1][nt & 1], bf[cur][nt >> 1][2 + (nt & 1)]);
        }
    }

    const int g   = lane >> 2;
    const int tig = lane & 3;
    const float* biasd = bias + (size_t)d * NTOT + n0 + wn * 32;
    CT* Cb = C + (size_t)(b * TT + m0 + wm * 64) * NTOT + n0 + wn * 32;

    #pragma unroll
    for (int nt = 0; nt < 4; nt++) {
        const int coff = nt * 8 + tig * 2;
        const float2 bb = *(const float2*)(biasd + coff);
        #pragma unroll
        for (int mt = 0; mt < 4; mt++) {
            const int r0 = mt * 16 + g;
            float2 v0, v1;
            v0.x = acc[mt][nt][0] + bb.x;  v0.y = acc[mt][nt][1] + bb.y;
            v1.x = acc[mt][nt][2] + bb.x;  v1.y = acc[mt][nt][3] + bb.y;
            if (RELU) {
                v0.x = fmaxf(v0.x, 0.0f); v0.y = fmaxf(v0.y, 0.0f);
                v1.x = fmaxf(v1.x, 0.0f); v1.y = fmaxf(v1.y, 0.0f);
            }
            if constexpr (sizeof(CT) == 2) {
                *(__half2*)((__half*)Cb + (size_t)r0 * NTOT + coff) =
                    __floats2half2_rn(v0.x, v0.y);
                *(__half2*)((__half*)Cb + (size_t)(r0 + 8) * NTOT + coff) =
                    __floats2half2_rn(v1.x, v1.y);
            } else {
                *(float2*)((float*)Cb + (size_t)r0 * NTOT + coff)       = v0;
                *(float2*)((float*)Cb + (size_t)(r0 + 8) * NTOT + coff) = v1;
            }
        }
    }
}

// ---------------------------------------------------------------- LayerNorm
// One warp per row of 512 floats; 8 rows per 256-thread block; no smem,
// no block barriers — pure warp-shuffle reduction + streaming float4 I/O.
__global__ __launch_bounds__(256) void ln_kernel(
    float*       __restrict__ y,      // [B*T, D_OUT], in-place
    const float* __restrict__ gamma,
    const float* __restrict__ beta,
    const int*   __restrict__ day)
{
    const int w    = threadIdx.x >> 5;            // warp in block: 0..7
    const int lane = threadIdx.x & 31;
    const int row  = blockIdx.x * 8 + w;          // 0 .. B*T-1
    const int b    = row >> 9;                    // row / TT
    const int d    = __ldg(day + b);

    const float4* yr = (const float4*)(y + (size_t)row * DOUT);

    // load 16 floats per lane: float4 at lane, lane+32, lane+64, lane+96
    float4 v[4];
    #pragma unroll
    for (int j = 0; j < 4; j++) v[j] = yr[lane + 32 * j];

    float s = 0.0f, sq = 0.0f;
    #pragma unroll
    for (int j = 0; j < 4; j++) {
        s  += v[j].x + v[j].y + v[j].z + v[j].w;
        sq += v[j].x * v[j].x + v[j].y * v[j].y
            + v[j].z * v[j].z + v[j].w * v[j].w;
    }
    #pragma unroll
    for (int off = 16; off; off >>= 1) {
        s  += __shfl_xor_sync(0xffffffffu, s,  off);
        sq += __shfl_xor_sync(0xffffffffu, sq, off);
    }

    const float mean = s * (1.0f / DOUT);
    const float var  = sq * (1.0f / DOUT) - mean * mean;
    const float inv  = rsqrtf(var + EPS_);

    const float4* gp = (const float4*)(gamma + (size_t)d * DOUT);
    const float4* zp = (const float4*)(beta  + (size_t)d * DOUT);
    float4* yw = (float4*)(y + (size_t)row * DOUT);

    #pragma unroll
    for (int j = 0; j < 4; j++) {
        const float4 gg = gp[lane + 32 * j];
        const float4 zz = zp[lane + 32 * j];
        float4 o;
        o.x = (v[j].x - mean) * inv * gg.x + zz.x;
        o.y = (v[j].y - mean) * inv * gg.y + zz.y;
        o.z = (v[j].z - mean) * inv * gg.z + zz.z;
        o.w = (v[j].w - mean) * inv * gg.w + zz.w;
        yw[lane + 32 * j] = o;
    }
}

// ---------------------------------------------------------------- launch
extern "C" void kernel_launch(void* const* d_in, const int* in_sizes, int n_in,
                              void* d_out, int out_size)
{
    const float* x     = (const float*)d_in[0];
    const int*   day   = (const int*)  d_in[1];
    const float* W1    = (const float*)d_in[2];
    const float* b1    = (const float*)d_in[3];
    const float* W2    = (const float*)d_in[4];
    const float* b2    = (const float*)d_in[5];
    const float* gamma = (const float*)d_in[6];
    const float* beta  = (const float*)d_in[7];
    float* out = (float*)d_out;

    __half *xh, *h, *wt1, *wt2;
    cudaGetSymbolAddress((void**)&xh,  g_xh);
    cudaGetSymbolAddress((void**)&h,   g_h);
    cudaGetSymbolAddress((void**)&wt1, g_wt1);
    cudaGetSymbolAddress((void**)&wt2, g_wt2);

    prep_kernel<<<NBLK_X + NBLK_W1 + NBLK_W2, 256>>>(
        (const float4*)x, (__half2*)xh, W1, wt1, W2, wt2);

    cudaFuncSetAttribute(gemm_mma<DIN,  DHID, true,  __half>,
                         cudaFuncAttributeMaxDynamicSharedMemorySize, SMEM_DYN);
    cudaFuncSetAttribute(gemm_mma<DHID, DOUT, false, float>,
                         cudaFuncAttributeMaxDynamicSharedMemorySize, SMEM_DYN);

    gemm_mma<DIN,  DHID, true,  __half><<<dim3(BB, TT / 128, DHID / 128), 256, SMEM_DYN>>>(
        xh, wt1, b1, day, h);
    gemm_mma<DHID, DOUT, false, float><<<dim3(BB, TT / 128, DOUT / 128), 256, SMEM_DYN>>>(
        h, wt2, b2, day, out);

    ln_kernel<<<BB * TT / 8, 256>>>(out, gamma, beta, day);
}